// round 2
// baseline (speedup 1.0000x reference)
#include <cuda_runtime.h>
#include <cstdint>

// Problem constants
#define BATCH 2
#define SEQ   2048
#define HEADS 16
#define HD    64
#define EMB   1024
#define MROWS (BATCH*SEQ)          // 4096
#define QKVN  (3*EMB)              // 3072

// Scratch (allocation-free rule: use __device__ globals)
__device__ float g_qkv[(size_t)MROWS * QKVN];   // 50.3 MB
__device__ float g_attn[(size_t)MROWS * EMB];   // 16.8 MB

// ---------------------------------------------------------------------------
// GEMM 1: qkv = x @ w_qkv, with RoPE fused into the epilogue for q,k columns.
// C[4096][3072] = A[4096][1024] * W[1024][3072]
// Tile 64x64, K-step 16, 256 threads, 4x4 micro-tile.
// ---------------------------------------------------------------------------
__global__ __launch_bounds__(256) void gemm_qkv_rope(
    const float* __restrict__ A,
    const float* __restrict__ W,
    const float* __restrict__ freqs)
{
    const int Kdim = EMB, Ndim = QKVN;
    __shared__ float As[16][68];   // As[k][m], padded for bank spread + 16B align
    __shared__ float Bs[16][68];   // Bs[k][n]

    const int tid = threadIdx.x;
    const int tx = tid & 15, ty = tid >> 4;
    const int m0 = blockIdx.y * 64;
    const int n0 = blockIdx.x * 64;

    float acc[4][4] = {};

    for (int k0 = 0; k0 < Kdim; k0 += 16) {
        {
            int k = tid & 15;
            int mb = tid >> 4;
            #pragma unroll
            for (int p = 0; p < 4; p++) {
                int m = mb + p * 16;
                As[k][m] = A[(size_t)(m0 + m) * Kdim + k0 + k];
            }
        }
        {
            int n = tid & 63;
            int kb = tid >> 6;
            #pragma unroll
            for (int p = 0; p < 4; p++) {
                int k = kb + p * 4;
                Bs[k][n] = W[(size_t)(k0 + k) * Ndim + n0 + n];
            }
        }
        __syncthreads();
        #pragma unroll
        for (int kk = 0; kk < 16; kk++) {
            float4 a4 = *(const float4*)&As[kk][ty * 4];
            float4 b4 = *(const float4*)&Bs[kk][tx * 4];
            float av[4] = {a4.x, a4.y, a4.z, a4.w};
            float bv[4] = {b4.x, b4.y, b4.z, b4.w};
            #pragma unroll
            for (int i = 0; i < 4; i++)
                #pragma unroll
                for (int j = 0; j < 4; j++)
                    acc[i][j] += av[i] * bv[j];
        }
        __syncthreads();
    }

    const int colb = n0 + tx * 4;
    #pragma unroll
    for (int i = 0; i < 4; i++) {
        const int row = m0 + ty * 4 + i;
        float4 o;
        if (colb < 2 * EMB) {
            // RoPE: col within q (0..1023) or k (1024..2047); d = col % 64.
            const int l  = row & (SEQ - 1);
            const int d0 = colb & (HD - 1);          // divisible by 4 -> two full pairs
            const float* f = &freqs[(size_t)l * HD + d0];  // freqs[l][d0/2][0..], flat = l*64 + d0
            float f00 = f[0], f01 = f[1], f10 = f[2], f11 = f[3];
            float a0 = acc[i][0], a1 = acc[i][1], a2 = acc[i][2], a3 = acc[i][3];
            o.x = a0 * f00 - a1 * f01;
            o.y = a1 * f00 + a0 * f01;
            o.z = a2 * f10 - a3 * f11;
            o.w = a3 * f10 + a2 * f11;
        } else {
            o = make_float4(acc[i][0], acc[i][1], acc[i][2], acc[i][3]);
        }
        *(float4*)&g_qkv[(size_t)row * QKVN + colb] = o;
    }
}

// ---------------------------------------------------------------------------
// Attention: flash-style, one block per (b, h, 64-row q tile).
// scores = (q*scale) @ k^T + bias ; online softmax ; acc = P @ v.
// 256 threads, 4x4 micro-tiles, fp32. Bias streamed with __ldcs (read-once).
// ---------------------------------------------------------------------------
#define APAD 68
__global__ __launch_bounds__(256) void attn_kernel(const float* __restrict__ bias)
{
    extern __shared__ float sm[];
    float* qT = sm;                  // qT[d][row]  (64 x APAD)
    float* kT = sm + 64 * APAD;      // kT[d][col]
    float* vs = sm + 2 * 64 * APAD;  // vs[c][d]
    float* pT = sm + 3 * 64 * APAD;  // pT[c][row]

    const int tid = threadIdx.x;
    const int tx = tid & 15, ty = tid >> 4;
    const int q0 = blockIdx.x * 64;
    const int h  = blockIdx.y;
    const int b  = blockIdx.z;
    const float scale = 0.125f;   // 1/sqrt(64)

    // Load q tile (transposed, pre-scaled)
    {
        const int d  = (tid & 15) * 4;
        const int rb = tid >> 4;
        #pragma unroll
        for (int p = 0; p < 4; p++) {
            int r = rb + p * 16;
            const float4 qv = *(const float4*)&g_qkv[(size_t)(b * SEQ + q0 + r) * QKVN + h * HD + d];
            qT[(d + 0) * APAD + r] = qv.x * scale;
            qT[(d + 1) * APAD + r] = qv.y * scale;
            qT[(d + 2) * APAD + r] = qv.z * scale;
            qT[(d + 3) * APAD + r] = qv.w * scale;
        }
    }

    float mrow[4], lrow[4], acc[4][4];
    #pragma unroll
    for (int i = 0; i < 4; i++) {
        mrow[i] = -1e30f; lrow[i] = 0.f;
        #pragma unroll
        for (int j = 0; j < 4; j++) acc[i][j] = 0.f;
    }

    for (int kt = 0; kt < SEQ / 64; kt++) {
        // Load k (transposed) and v tiles
        {
            const int d  = (tid & 15) * 4;
            const int rb = tid >> 4;
            #pragma unroll
            for (int p = 0; p < 4; p++) {
                int r = rb + p * 16;
                size_t base = (size_t)(b * SEQ + kt * 64 + r) * QKVN + h * HD + d;
                float4 kv = *(const float4*)&g_qkv[base + EMB];
                kT[(d + 0) * APAD + r] = kv.x;
                kT[(d + 1) * APAD + r] = kv.y;
                kT[(d + 2) * APAD + r] = kv.z;
                kT[(d + 3) * APAD + r] = kv.w;
                float4 vv = *(const float4*)&g_qkv[base + 2 * EMB];
                *(float4*)&vs[r * APAD + d] = vv;
            }
        }
        __syncthreads();   // k/v (and q, first iter) visible; prior-iter reads done

        // scores
        float s[4][4] = {};
        #pragma unroll
        for (int d = 0; d < 64; d++) {
            float4 qa = *(const float4*)&qT[d * APAD + ty * 4];
            float4 kb = *(const float4*)&kT[d * APAD + tx * 4];
            float qv[4] = {qa.x, qa.y, qa.z, qa.w};
            float kv[4] = {kb.x, kb.y, kb.z, kb.w};
            #pragma unroll
            for (int i = 0; i < 4; i++)
                #pragma unroll
                for (int j = 0; j < 4; j++)
                    s[i][j] += qv[i] * kv[j];
        }
        // + bias (streamed, read-once)
        #pragma unroll
        for (int i = 0; i < 4; i++) {
            const float4 bb = __ldcs((const float4*)&bias[((size_t)h * SEQ + q0 + ty * 4 + i) * SEQ + kt * 64 + tx * 4]);
            s[i][0] += bb.x; s[i][1] += bb.y; s[i][2] += bb.z; s[i][3] += bb.w;
        }
        // online softmax (row groups are 16 aligned lanes: shfl.xor 8,4,2,1)
        #pragma unroll
        for (int i = 0; i < 4; i++) {
            float tm = fmaxf(fmaxf(s[i][0], s[i][1]), fmaxf(s[i][2], s[i][3]));
            #pragma unroll
            for (int off = 8; off >= 1; off >>= 1)
                tm = fmaxf(tm, __shfl_xor_sync(0xffffffffu, tm, off));
            const float mn = fmaxf(mrow[i], tm);
            const float alpha = __expf(mrow[i] - mn);
            mrow[i] = mn;
            float ts = 0.f;
            #pragma unroll
            for (int j = 0; j < 4; j++) { s[i][j] = __expf(s[i][j] - mn); ts += s[i][j]; }
            #pragma unroll
            for (int off = 8; off >= 1; off >>= 1)
                ts += __shfl_xor_sync(0xffffffffu, ts, off);
            lrow[i] = lrow[i] * alpha + ts;
            #pragma unroll
            for (int j = 0; j < 4; j++) acc[i][j] *= alpha;
        }
        // write P transposed: pT[col][row]
        #pragma unroll
        for (int j = 0; j < 4; j++) {
            float4 pv = make_float4(s[0][j], s[1][j], s[2][j], s[3][j]);
            *(float4*)&pT[(tx * 4 + j) * APAD + ty * 4] = pv;
        }
        __syncthreads();   // pT visible
        // acc += P @ V
        #pragma unroll
        for (int c = 0; c < 64; c++) {
            float4 pa = *(const float4*)&pT[c * APAD + ty * 4];
            float4 vb = *(const float4*)&vs[c * APAD + tx * 4];
            float pv[4] = {pa.x, pa.y, pa.z, pa.w};
            float vv[4] = {vb.x, vb.y, vb.z, vb.w};
            #pragma unroll
            for (int i = 0; i < 4; i++)
                #pragma unroll
                for (int j = 0; j < 4; j++)
                    acc[i][j] += pv[i] * vv[j];
        }
        __syncthreads();   // PV reads done before next tile overwrites
    }

    #pragma unroll
    for (int i = 0; i < 4; i++) {
        const float inv = 1.0f / lrow[i];
        float4 ov = make_float4(acc[i][0] * inv, acc[i][1] * inv, acc[i][2] * inv, acc[i][3] * inv);
        *(float4*)&g_attn[(size_t)(b * SEQ + q0 + ty * 4 + i) * EMB + h * HD + tx * 4] = ov;
    }
}

// ---------------------------------------------------------------------------
// GEMM 3: out = g_attn @ w_proj + b_proj
// C[4096][1024] = A[4096][1024] * W[1024][1024]
// ---------------------------------------------------------------------------
__global__ __launch_bounds__(256) void gemm_proj(
    const float* __restrict__ W,
    const float* __restrict__ bproj,
    float* __restrict__ out)
{
    const int Kdim = EMB, Ndim = EMB;
    __shared__ float As[16][68];
    __shared__ float Bs[16][68];

    const int tid = threadIdx.x;
    const int tx = tid & 15, ty = tid >> 4;
    const int m0 = blockIdx.y * 64;
    const int n0 = blockIdx.x * 64;

    float acc[4][4] = {};

    for (int k0 = 0; k0 < Kdim; k0 += 16) {
        {
            int k = tid & 15;
            int mb = tid >> 4;
            #pragma unroll
            for (int p = 0; p < 4; p++) {
                int m = mb + p * 16;
                As[k][m] = g_attn[(size_t)(m0 + m) * Kdim + k0 + k];
            }
        }
        {
            int n = tid & 63;
            int kb = tid >> 6;
            #pragma unroll
            for (int p = 0; p < 4; p++) {
                int k = kb + p * 4;
                Bs[k][n] = W[(size_t)(k0 + k) * Ndim + n0 + n];
            }
        }
        __syncthreads();
        #pragma unroll
        for (int kk = 0; kk < 16; kk++) {
            float4 a4 = *(const float4*)&As[kk][ty * 4];
            float4 b4 = *(const float4*)&Bs[kk][tx * 4];
            float av[4] = {a4.x, a4.y, a4.z, a4.w};
            float bv[4] = {b4.x, b4.y, b4.z, b4.w};
            #pragma unroll
            for (int i = 0; i < 4; i++)
                #pragma unroll
                for (int j = 0; j < 4; j++)
                    acc[i][j] += av[i] * bv[j];
        }
        __syncthreads();
    }

    const int colb = n0 + tx * 4;
    const float4 bp = *(const float4*)&bproj[colb];
    #pragma unroll
    for (int i = 0; i < 4; i++) {
        const int row = m0 + ty * 4 + i;
        float4 o = make_float4(acc[i][0] + bp.x, acc[i][1] + bp.y,
                               acc[i][2] + bp.z, acc[i][3] + bp.w);
        *(float4*)&out[(size_t)row * Ndim + colb] = o;
    }
}

// ---------------------------------------------------------------------------
extern "C" void kernel_launch(void* const* d_in, const int* in_sizes, int n_in,
                              void* d_out, int out_size)
{
    const float* x      = (const float*)d_in[0];  // (2,2048,1024)
    const float* freqs  = (const float*)d_in[1];  // (2048,32,2)
    const float* bias   = (const float*)d_in[2];  // (1,16,2048,2048)
    const float* w_qkv  = (const float*)d_in[3];  // (1024,3072)
    const float* w_proj = (const float*)d_in[4];  // (1024,1024)
    const float* b_proj = (const float*)d_in[5];  // (1024,)
    float* out = (float*)d_out;                   // (2,2048,1024)

    const int attn_smem = 4 * 64 * APAD * sizeof(float);  // 69632 B
    cudaFuncSetAttribute(attn_kernel, cudaFuncAttributeMaxDynamicSharedMemorySize, attn_smem);

    // 1) QKV GEMM + RoPE
    gemm_qkv_rope<<<dim3(QKVN / 64, MROWS / 64), 256>>>(x, w_qkv, freqs);
    // 2) attention
    attn_kernel<<<dim3(SEQ / 64, HEADS, BATCH), 256, attn_smem>>>(bias);
    // 3) output projection + bias
    gemm_proj<<<dim3(EMB / 64, MROWS / 64), 256>>>(w_proj, b_proj, out);
}